// round 17
// baseline (speedup 1.0000x reference)
#include <cuda_runtime.h>
#include <cuda_bf16.h>
#include <cuda_fp16.h>
#include <math.h>
#include <stdint.h>

// Problem constants
#define MTOT 4096      // B*S
#define SEQ  2048
#define HID  2048
#define NH   16
#define NKV  4
#define HD   128
#define QW   2048      // NH*HD
#define KVW  512       // NKV*HD
#define W2   2560      // fused Q|K weight width (bf16 3-term path)

// Scratch (allocation-free rule: __device__ globals)
__device__ __nv_bfloat16 g_xh[(size_t)MTOT * HID];
__device__ __nv_bfloat16 g_xl[(size_t)MTOT * HID];
__device__ __half        g_xf[(size_t)MTOT * HID];
__device__ __nv_bfloat16 g_wh[(size_t)W2 * HID];
__device__ __nv_bfloat16 g_wl[(size_t)W2 * HID];
__device__ __half        g_vwf[(size_t)KVW * HID];
__device__ __half        g_owf[(size_t)HID * QW];
__device__ __nv_bfloat16 g_Qh[(size_t)MTOT * QW];
__device__ __nv_bfloat16 g_Ql[(size_t)MTOT * QW];
__device__ __nv_bfloat16 g_Kh[(size_t)MTOT * KVW];
__device__ __nv_bfloat16 g_Kl[(size_t)MTOT * KVW];
__device__ __half        g_Vf[(size_t)MTOT * KVW];
__device__ __half        g_Af[(size_t)MTOT * QW];

// ---------------------------------------------------------------------------
// helpers
// ---------------------------------------------------------------------------
__device__ __forceinline__ void mma16816(float* c, const uint32_t* a, uint32_t b0, uint32_t b1) {
    asm volatile(
        "mma.sync.aligned.m16n8k16.row.col.f32.bf16.bf16.f32 "
        "{%0,%1,%2,%3}, {%4,%5,%6,%7}, {%8,%9}, {%0,%1,%2,%3};"
        : "+f"(c[0]), "+f"(c[1]), "+f"(c[2]), "+f"(c[3])
        : "r"(a[0]), "r"(a[1]), "r"(a[2]), "r"(a[3]), "r"(b0), "r"(b1));
}
__device__ __forceinline__ void mma16816f(float* c, const uint32_t* a, uint32_t b0, uint32_t b1) {
    asm volatile(
        "mma.sync.aligned.m16n8k16.row.col.f32.f16.f16.f32 "
        "{%0,%1,%2,%3}, {%4,%5,%6,%7}, {%8,%9}, {%0,%1,%2,%3};"
        : "+f"(c[0]), "+f"(c[1]), "+f"(c[2]), "+f"(c[3])
        : "r"(a[0]), "r"(a[1]), "r"(a[2]), "r"(a[3]), "r"(b0), "r"(b1));
}
__device__ __forceinline__ void ldm4(uint32_t* r, uint32_t a) {
    asm volatile("ldmatrix.sync.aligned.m8n8.x4.shared.b16 {%0,%1,%2,%3}, [%4];"
                 : "=r"(r[0]), "=r"(r[1]), "=r"(r[2]), "=r"(r[3]) : "r"(a));
}
__device__ __forceinline__ void ldm4t(uint32_t* r, uint32_t a) {
    asm volatile("ldmatrix.sync.aligned.m8n8.x4.trans.shared.b16 {%0,%1,%2,%3}, [%4];"
                 : "=r"(r[0]), "=r"(r[1]), "=r"(r[2]), "=r"(r[3]) : "r"(a));
}
__device__ __forceinline__ uint32_t smem_u32(const void* p) {
    uint32_t a;
    asm("{ .reg .u64 tmp; cvta.to.shared.u64 tmp, %1; cvt.u32.u64 %0, tmp; }"
        : "=r"(a) : "l"(p));
    return a;
}
__device__ __forceinline__ void cpa16(uint32_t dst, const void* src) {
    asm volatile("cp.async.cg.shared.global [%0], [%1], 16;" :: "r"(dst), "l"(src));
}
#define CPA_COMMIT() asm volatile("cp.async.commit_group;" ::: "memory")
#define CPA_WAIT(n)  asm volatile("cp.async.wait_group %0;" :: "n"(n) : "memory")

__device__ __forceinline__ void split2(float a, float b, uint32_t& h, uint32_t& l) {
    __nv_bfloat162 hh = __floats2bfloat162_rn(a, b);
    float ra = a - __bfloat162float(hh.x);
    float rb = b - __bfloat162float(hh.y);
    __nv_bfloat162 ll = __floats2bfloat162_rn(ra, rb);
    h = *(uint32_t*)&hh;
    l = *(uint32_t*)&ll;
}
__device__ __forceinline__ uint32_t packh2(float a, float b) {
    __half2 h = __floats2half2_rn(a, b);
    return *(uint32_t*)&h;
}

// ---------------------------------------------------------------------------
// Fused split kernel
// ---------------------------------------------------------------------------
#define N4_X   (MTOT * HID / 4)
#define N4_QW  (QW * HID / 4)
#define N4_KW  (KVW * HID / 4)
#define N4_ALL (N4_X + N4_QW + 2 * N4_KW + N4_QW)

__global__ void split_all(const float* __restrict__ x, const float* __restrict__ qw,
                          const float* __restrict__ kw, const float* __restrict__ vw,
                          const float* __restrict__ ow,
                          __nv_bfloat16* __restrict__ xh, __nv_bfloat16* __restrict__ xl,
                          __half* __restrict__ xf,
                          __nv_bfloat16* __restrict__ wh, __nv_bfloat16* __restrict__ wl,
                          __half* __restrict__ vwf, __half* __restrict__ owf)
{
    int i = blockIdx.x * blockDim.x + threadIdx.x;
    if (i >= N4_ALL) return;
    int j = i;
    if (j < N4_X) {
        float4 v = ((const float4*)x)[j];
        uint32_t h0, l0, h1, l1;
        split2(v.x, v.y, h0, l0);
        split2(v.z, v.w, h1, l1);
        ((uint2*)xh)[j] = make_uint2(h0, h1);
        ((uint2*)xl)[j] = make_uint2(l0, l1);
        ((uint2*)xf)[j] = make_uint2(packh2(v.x, v.y), packh2(v.z, v.w));
        return;
    }
    j -= N4_X;
    if (j < N4_QW) {
        float4 v = ((const float4*)qw)[j];
        uint32_t h0, l0, h1, l1;
        split2(v.x, v.y, h0, l0);
        split2(v.z, v.w, h1, l1);
        ((uint2*)wh)[j] = make_uint2(h0, h1);
        ((uint2*)wl)[j] = make_uint2(l0, l1);
        return;
    }
    j -= N4_QW;
    if (j < N4_KW) {
        float4 v = ((const float4*)kw)[j];
        uint32_t h0, l0, h1, l1;
        split2(v.x, v.y, h0, l0);
        split2(v.z, v.w, h1, l1);
        size_t off = (size_t)QW * HID / 4;
        ((uint2*)wh)[off + j] = make_uint2(h0, h1);
        ((uint2*)wl)[off + j] = make_uint2(l0, l1);
        return;
    }
    j -= N4_KW;
    if (j < N4_KW) {
        float4 v = ((const float4*)vw)[j];
        ((uint2*)vwf)[j] = make_uint2(packh2(v.x, v.y), packh2(v.z, v.w));
        return;
    }
    j -= N4_KW;
    {
        float4 v = ((const float4*)ow)[j];
        ((uint2*)owf)[j] = make_uint2(packh2(v.x, v.y), packh2(v.z, v.w));
    }
}

// ---------------------------------------------------------------------------
// QK GEMM (bf16 3-term) + rope/split epilogue. BM=64, BN=128 -> 1280 CTAs.
// 2-stage cp.async double buffer AND 3 CTAs/SM (stage 30720B, total 61440B).
// Per-accumulator MMA order unchanged -> bit-identical.
// ---------------------------------------------------------------------------
#define GROW  80
#define GTA   (64 * GROW)             // 5120 B  (A tile, 64 rows)
#define GTB   (128 * GROW)            // 10240 B (B tile, 128 rows)
#define QK_STG (2 * GTA + 2 * GTB)    // 30720 B per stage
#define QK_SMEM (2 * QK_STG)          // 61440 B

__global__ __launch_bounds__(128, 3)
void hmma_gemm_qk(const __nv_bfloat16* __restrict__ Ah, const __nv_bfloat16* __restrict__ Al,
                  const __nv_bfloat16* __restrict__ Bh, const __nv_bfloat16* __restrict__ Bl,
                  __nv_bfloat16* __restrict__ Qoh, __nv_bfloat16* __restrict__ Qol,
                  __nv_bfloat16* __restrict__ Koh, __nv_bfloat16* __restrict__ Kol,
                  const float* __restrict__ sinp, const float* __restrict__ cosp,
                  int M, int N, int K)
{
    extern __shared__ __align__(128) char smem[];
    const uint32_t sb = smem_u32(smem);

    const int t    = threadIdx.x;
    const int warp = t >> 5;
    const int lane = t & 31;
    const int wm   = warp >> 1;
    const int wn   = warp & 1;
    const int bm   = blockIdx.y * 64;
    const int bn   = blockIdx.x * 128;

    float acc[2][8][4];
#pragma unroll
    for (int mi = 0; mi < 2; mi++)
#pragma unroll
        for (int ni = 0; ni < 8; ni++)
#pragma unroll
            for (int r = 0; r < 4; r++) acc[mi][ni][r] = 0.f;

    const int S = K / 32;

    auto issue = [&](int s, int buf) {
        const int k0 = s * 32;
        const uint32_t stg = sb + (uint32_t)buf * QK_STG;
#pragma unroll
        for (int i = 0; i < 2; i++) {
            int f = i * 128 + t;
            int r = f >> 2, ch = f & 3;
            uint32_t so = r * GROW + ch * 16;
            size_t  go = (size_t)(bm + r) * K + k0 + ch * 8;
            cpa16(stg + so, Ah + go);
            cpa16(stg + GTA + so, Al + go);
        }
#pragma unroll
        for (int i = 0; i < 4; i++) {
            int f = i * 128 + t;
            int r = f >> 2, ch = f & 3;
            uint32_t so = r * GROW + ch * 16;
            size_t  go = (size_t)(bn + r) * K + k0 + ch * 8;
            cpa16(stg + 2 * GTA + so, Bh + go);
            cpa16(stg + 2 * GTA + GTB + so, Bl + go);
        }
        CPA_COMMIT();
    };

    issue(0, 0);

    for (int s = 0; s < S; s++) {
        const int buf = s & 1;
        if (s + 1 < S) { issue(s + 1, buf ^ 1); CPA_WAIT(1); }
        else           { CPA_WAIT(0); }
        __syncthreads();

        const uint32_t smAh = sb + (uint32_t)buf * QK_STG;
        const uint32_t smAl = smAh + GTA;
        const uint32_t smBh = smAh + 2 * GTA;
        const uint32_t smBl = smAh + 2 * GTA + GTB;

#pragma unroll
        for (int kk = 0; kk < 2; kk++) {
            // phase 1: terms hh + lh
            {
                uint32_t bh[4][4];
#pragma unroll
                for (int ng = 0; ng < 4; ng++) {
                    int rr = wn * 64 + ng * 16 + (lane & 15);
                    ldm4(bh[ng], smBh + rr * GROW + (kk * 2 + (lane >> 4)) * 16);
                }
#pragma unroll
                for (int mt = 0; mt < 2; mt++) {
                    uint32_t ah[4], al[4];
                    int rr = wm * 32 + mt * 16 + (lane & 15);
                    uint32_t ad = rr * GROW + (kk * 2 + (lane >> 4)) * 16;
                    ldm4(ah, smAh + ad);
                    ldm4(al, smAl + ad);
#pragma unroll
                    for (int n8 = 0; n8 < 8; n8++) {
                        int ng = n8 >> 1, hf = n8 & 1;
                        mma16816(acc[mt][n8], ah, bh[ng][hf], bh[ng][hf + 2]);
                    }
#pragma unroll
                    for (int n8 = 0; n8 < 8; n8++) {
                        int ng = n8 >> 1, hf = n8 & 1;
                        mma16816(acc[mt][n8], al, bh[ng][hf], bh[ng][hf + 2]);
                    }
                }
            }
            // phase 2: term hl
            {
                uint32_t bl[4][4];
#pragma unroll
                for (int ng = 0; ng < 4; ng++) {
                    int rr = wn * 64 + ng * 16 + (lane & 15);
                    ldm4(bl[ng], smBl + rr * GROW + (kk * 2 + (lane >> 4)) * 16);
                }
#pragma unroll
                for (int mt = 0; mt < 2; mt++) {
                    uint32_t ah[4];
                    int rr = wm * 32 + mt * 16 + (lane & 15);
                    ldm4(ah, smAh + rr * GROW + (kk * 2 + (lane >> 4)) * 16);
#pragma unroll
                    for (int n8 = 0; n8 < 8; n8++) {
                        int ng = n8 >> 1, hf = n8 & 1;
                        mma16816(acc[mt][n8], ah, bl[ng][hf], bl[ng][hf + 2]);
                    }
                }
            }
        }
        __syncthreads();
    }

    // Epilogue: stage 64 rows, rope + bf16 split
    const int g   = lane >> 2;
    const int tig = lane & 3;
    float* stg = (float*)smem;   // [64][132] = 33792 B
    const int bx = blockIdx.x;

#pragma unroll
    for (int mt = 0; mt < 2; mt++)
#pragma unroll
        for (int n8 = 0; n8 < 8; n8++) {
            int row = wm * 32 + mt * 16 + g;
            int col = wn * 64 + n8 * 8 + tig * 2;
            stg[row * 132 + col]     = acc[mt][n8][0];
            stg[row * 132 + col + 1] = acc[mt][n8][1];
            stg[(row + 8) * 132 + col]     = acc[mt][n8][2];
            stg[(row + 8) * 132 + col + 1] = acc[mt][n8][3];
        }
    __syncthreads();

    {
        const int r2   = t >> 1;
        const int half = t & 1;
        const int gm   = bm + r2;
        const int spos = gm & (SEQ - 1);
        const int pb   = half * 32;

        bool isQ = bx < 16;
        __nv_bfloat16* dh = isQ ? (Qoh + (size_t)gm * QW + bx * 128)
                                : (Koh + (size_t)gm * KVW + (bx - 16) * 128);
        __nv_bfloat16* dl = isQ ? (Qol + (size_t)gm * QW + bx * 128)
                                : (Kol + (size_t)gm * KVW + (bx - 16) * 128);

        uint32_t h0[16], l0[16], h1[16], l1[16];
#pragma unroll
        for (int j = 0; j < 16; j++) {
            int pi = pb + j * 2;
            float x0a = stg[r2 * 132 + pi],      x0b = stg[r2 * 132 + pi + 1];
            float x1a = stg[r2 * 132 + pi + 64], x1b = stg[r2 * 132 + pi + 65];
            float ca = cosp[(size_t)spos * HD + pi],  cb = cosp[(size_t)spos * HD + pi + 1];
            float sa = sinp[(size_t)spos * HD + pi],  sbv = sinp[(size_t)spos * HD + pi + 1];
            float y0a = x0a * ca - x1a * sa,  y1a = x1a * ca + x0a * sa;
            float y0b = x0b * cb - x1b * sbv, y1b = x1b * cb + x0b * sbv;
            split2(y0a, y0b, h0[j], l0[j]);
            split2(y1a, y1b, h1[j], l1[j]);
        }
#pragma unroll
        for (int w = 0; w < 4; w++) {
            *(uint4*)(dh + pb + w * 8)      = ((uint4*)h0)[w];
            *(uint4*)(dh + 64 + pb + w * 8) = ((uint4*)h1)[w];
            *(uint4*)(dl + pb + w * 8)      = ((uint4*)l0)[w];
            *(uint4*)(dl + 64 + pb + w * 8) = ((uint4*)l1)[w];
        }
    }
}

// ---------------------------------------------------------------------------
// 1-term fp16 GEMM, BM=64, BN=128. OUTF16=1 -> fp16 out, 0 -> fp32 out.
// ---------------------------------------------------------------------------
#define OST   (GTA + GTB)            // 15360 B per stage
#define OSMEM (2 * OST)              // 30720 B

template<int OUTF16>
__global__ __launch_bounds__(128, 3)
void hmma_gemm_1t(const __half* __restrict__ A_, const __half* __restrict__ B_,
                  void* __restrict__ Cv, int M, int N, int K)
{
    extern __shared__ __align__(128) char smem[];
    const uint32_t sb = smem_u32(smem);

    const int t    = threadIdx.x;
    const int warp = t >> 5;
    const int lane = t & 31;
    const int wm   = warp >> 1;
    const int wn   = warp & 1;
    const int bm   = blockIdx.y * 64;
    const int bn   = blockIdx.x * 128;

    float acc[2][8][4];
#pragma unroll
    for (int mi = 0; mi < 2; mi++)
#pragma unroll
        for (int ni = 0; ni < 8; ni++)
#pragma unroll
            for (int r = 0; r < 4; r++) acc[mi][ni][r] = 0.f;

    const int S = K / 32;

    auto issue = [&](int s, int buf) {
        const int k0 = s * 32;
        const uint32_t stg = sb + (uint32_t)buf * OST;
#pragma unroll
        for (int i = 0; i < 2; i++) {
            int f = i * 128 + t;
            int r = f >> 2, ch = f & 3;
            cpa16(stg + r * GROW + ch * 16, A_ + (size_t)(bm + r) * K + k0 + ch * 8);
        }
#pragma unroll
        for (int i = 0; i < 4; i++) {
            int f = i * 128 + t;
            int r = f >> 2, ch = f & 3;
            cpa16(stg + GTA + r * GROW + ch * 16, B_ + (size_t)(bn + r) * K + k0 + ch * 8);
        }
        CPA_COMMIT();
    };

    issue(0, 0);

    for (int s = 0; s < S; s++) {
        const int buf = s & 1;
        if (s + 1 < S) { issue(s + 1, buf ^ 1); CPA_WAIT(1); }
        else           { CPA_WAIT(0); }
        __syncthreads();

        const uint32_t smA = sb + (uint32_t)buf * OST;
        const uint32_t smB = smA + GTA;

#pragma unroll
        for (int kk = 0; kk < 2; kk++) {
            uint32_t bfr[4][4];
#pragma unroll
            for (int ng = 0; ng < 4; ng++) {
                int rr = wn * 64 + ng * 16 + (lane & 15);
                uint32_t ad = rr * GROW + (kk * 2 + (lane >> 4)) * 16;
                ldm4(bfr[ng], smB + ad);
            }
#pragma unroll
            for (int mt = 0; mt < 2; mt++) {
                uint32_t af[4];
                int rr = wm * 32 + mt * 16 + (lane & 15);
                uint32_t ad = rr * GROW + (kk * 2 + (lane >> 4)) * 16;
                ldm4(af, smA + ad);
#pragma unroll
                for (int n8 = 0; n8 < 8; n8++) {
                    int ng = n8 >> 1, hf = n8 & 1;
                    mma16816f(acc[mt][n8], af, bfr[ng][hf], bfr[ng][hf + 2]);
                }
            }
        }
        __syncthreads();
    }

    const int g   = lane >> 2;
    const int tig = lane & 3;
    if (OUTF16) {
        __half* C = (__half*)Cv;
#pragma unroll
        for (int mt = 0; mt < 2; mt++)
#pragma unroll
            for (int n8 = 0; n8 < 8; n8++) {
                int row = bm + wm * 32 + mt * 16 + g;
                int col = bn + wn * 64 + n8 * 8 + tig * 2;
                *(uint32_t*)(C + (size_t)row * N + col) = packh2(acc[mt][n8][0], acc[mt][n8][1]);
                *(uint32_t*)(C + (size_t)(row + 8) * N + col) = packh2(acc[mt][n8][2], acc[mt][n8][3]);
            }
    } else {
        float* C = (float*)Cv;
#pragma unroll
        for (int mt = 0; mt < 2; mt++)
#pragma unroll
            for (int n8 = 0; n8 < 8; n8++) {
                int row = bm + wm * 32 + mt * 16 + g;
                int col = bn + wn * 64 + n8 * 8 + tig * 2;
                *(float2*)(C + (size_t)row * N + col) = make_float2(acc[mt][n8][0], acc[mt][n8][1]);
                *(float2*)(C + (size_t)(row + 8) * N + col) = make_float2(acc[mt][n8][2], acc[mt][n8][3]);
            }
    }
}

// ---------------------------------------------------------------------------
// Flash attention: one qt per CTA, LPT (descending-work) bid->qt mapping.
// QK bf16 3-term; PV single fp16 MMA; single-fp16 output.
// ---------------------------------------------------------------------------
#define AT_TILE 16384
#define AT_SMEM (5 * AT_TILE)               // 81920 B
#define NQT     (SEQ / 64)                  // 32

__device__ __forceinline__ uint32_t swz256(int r, int ch) {
    return (uint32_t)(r * 256 + (((ch ^ (r & 7)) & 15) << 4));
}

__global__ __launch_bounds__(128)
void flash_attn_mma(const __nv_bfloat16* __restrict__ Qh, const __nv_bfloat16* __restrict__ Ql,
                    const __nv_bfloat16* __restrict__ Kh, const __nv_bfloat16* __restrict__ Kl,
                    const __half* __restrict__ Vf, __half* __restrict__ OAf)
{
    extern __shared__ __align__(128) char smem[];
    const uint32_t sb  = smem_u32(smem);
    const uint32_t sQh = sb;
    const uint32_t sQl = sb + AT_TILE;
    const uint32_t sA  = sb + 2 * AT_TILE;
    const uint32_t sBv = sb + 4 * AT_TILE;

    // LPT mapping: biggest qt first
    const int bid = blockIdx.x;
    const int qt  = (NQT - 1) - (bid >> 5);
    const int hb  = bid & 31;
    const int h   = hb >> 1;
    const int b   = hb & 1;
    const int kvh = h >> 2;
    const int q0  = qt * 64;

    const int t    = threadIdx.x;
    const int warp = t >> 5;
    const int lane = t & 31;
    const int g    = lane >> 2;
    const int tig  = lane & 3;

    const int rl = warp * 16 + g;
    const int rh = rl + 8;

    auto load_k = [&](int kt) {
        const __nv_bfloat16* bh = Kh + (size_t)(b * SEQ + kt * 64) * KVW + kvh * HD;
        const __nv_bfloat16* bl = Kl + (size_t)(b * SEQ + kt * 64) * KVW + kvh * HD;
#pragma unroll
        for (int i = 0; i < 8; i++) {
            int f = i * 128 + t;
            int r = f >> 4, ch = f & 15;
            cpa16(sA + swz256(r, ch),           bh + (size_t)r * KVW + ch * 8);
            cpa16(sA + AT_TILE + swz256(r, ch), bl + (size_t)r * KVW + ch * 8);
        }
        CPA_COMMIT();
    };
    auto load_v = [&](int kt) {
        const __half* bv = Vf + (size_t)(b * SEQ + kt * 64) * KVW + kvh * HD;
#pragma unroll
        for (int i = 0; i < 8; i++) {
            int f = i * 128 + t;
            int r = f >> 4, ch = f & 15;
            cpa16(sBv + swz256(r, ch), bv + (size_t)r * KVW + ch * 8);
        }
        CPA_COMMIT();
    };

    {
        const __nv_bfloat16* qbh = Qh + (size_t)(b * SEQ + q0) * QW + h * HD;
        const __nv_bfloat16* qbl = Ql + (size_t)(b * SEQ + q0) * QW + h * HD;
#pragma unroll
        for (int i = 0; i < 8; i++) {
            int f = i * 128 + t;
            int r = f >> 4, ch = f & 15;
            cpa16(sQh + swz256(r, ch), qbh + (size_t)r * QW + ch * 8);
            cpa16(sQl + swz256(r, ch), qbl + (size_t)r * QW + ch * 8);
        }
        CPA_COMMIT();
    }
    load_k(0);
    CPA_WAIT(0);
    __syncthreads();

    float o[16][4];
    float m0 = -1e30f, m1 = -1e30f, l0 = 0.f, l1 = 0.f;
#pragma unroll
    for (int i = 0; i < 16; i++)
#pragma unroll
        for (int j = 0; j < 4; j++) o[i][j] = 0.f;

    for (int kt = 0; kt <= qt; kt++) {
        load_v(kt);

        float sacc[8][4];
#pragma unroll
        for (int i = 0; i < 8; i++)
#pragma unroll
            for (int j = 0; j < 4; j++) sacc[i][j] = 0.f;

#pragma unroll
        for (int ks = 0; ks < 8; ks++) {
            uint32_t qfh[4], qfl[4];
            {
                int rr = warp * 16 + (lane & 15);
                uint32_t ad = swz256(rr, ks * 2 + (lane >> 4));
                ldm4(qfh, sQh + ad);
                ldm4(qfl, sQl + ad);
            }
            uint32_t kfh[4][4], kfl[4][4];
#pragma unroll
            for (int ng = 0; ng < 4; ng++) {
                int rr = ng * 16 + (lane & 15);
                uint32_t ad = swz256(rr, ks * 2 + (lane >> 4));
                ldm4(kfh[ng], sA + ad);
                ldm4(kfl[ng], sA + AT_TILE + ad);
            }
#pragma unroll
            for (int n8 = 0; n8 < 8; n8++) {
                int ng = n8 >> 1, hf = n8 & 1;
                mma16816(sacc[n8], qfh, kfh[ng][hf], kfh[ng][hf + 2]);
            }
#pragma unroll
            for (int n8 = 0; n8 < 8; n8++) {
                int ng = n8 >> 1, hf = n8 & 1;
                mma16816(sacc[n8], qfl, kfh[ng][hf], kfh[ng][hf + 2]);
            }
#pragma unroll
            for (int n8 = 0; n8 < 8; n8++) {
                int ng = n8 >> 1, hf = n8 & 1;
                mma16816(sacc[n8], qfh, kfl[ng][hf], kfl[ng][hf + 2]);
            }
        }

        if (kt == qt) {
#pragma unroll
            for (int n8 = 0; n8 < 8; n8++) {
                int c0 = n8 * 8 + tig * 2, c1 = c0 + 1;
                if (c0 > rl) sacc[n8][0] = -1e30f;
                if (c1 > rl) sacc[n8][1] = -1e30f;
                if (c0 > rh) sacc[n8][2] = -1e30f;
                if (c1 > rh) sacc[n8][3] = -1e30f;
            }
        }

        float mx0 = -1e30f, mx1 = -1e30f;
#pragma unroll
        for (int n8 = 0; n8 < 8; n8++) {
            mx0 = fmaxf(mx0, fmaxf(sacc[n8][0], sacc[n8][1]));
            mx1 = fmaxf(mx1, fmaxf(sacc[n8][2], sacc[n8][3]));
        }
        mx0 = fmaxf(mx0, __shfl_xor_sync(0xffffffffu, mx0, 1));
        mx0 = fmaxf(mx0, __shfl_xor_sync(0xffffffffu, mx0, 2));
        mx1 = fmaxf(mx1, __shfl_xor_sync(0xffffffffu, mx1, 1));
        mx1 = fmaxf(mx1, __shfl_xor_sync(0xffffffffu, mx1, 2));

        float mn0 = fmaxf(m0, mx0), mn1 = fmaxf(m1, mx1);
        float al0 = __expf(m0 - mn0), al1 = __expf(m1 - mn1);
        m0 = mn0; m1 = mn1;

        float s0 = 0.f, s1 = 0.f;
#pragma unroll
        for (int n8 = 0; n8 < 8; n8++) {
            float p0 = __expf(sacc[n8][0] - m0);
            float p1 = __expf(sacc[n8][1] - m0);
            float p2 = __expf(sacc[n8][2] - m1);
            float p3 = __expf(sacc[n8][3] - m1);
            sacc[n8][0] = p0; sacc[n8][1] = p1; sacc[n8][2] = p2; sacc[n8][3] = p3;
            s0 += p0 + p1; s1 += p2 + p3;
        }
        s0 += __shfl_xor_sync(0xffffffffu, s0, 1);
        s0 += __shfl_xor_sync(0xffffffffu, s0, 2);
        s1 += __shfl_xor_sync(0xffffffffu, s1, 1);
        s1 += __shfl_xor_sync(0xffffffffu, s1, 2);
        l0 = l0 * al0 + s0;
        l1 = l1 * al1 + s1;

#pragma unroll
        for (int i = 0; i < 16; i++) {
            o[i][0] *= al0; o[i][1] *= al0;
            o[i][2] *= al1; o[i][3] *= al1;
        }

        uint32_t ph[4][4];
#pragma unroll
        for (int kk = 0; kk < 4; kk++) {
            ph[kk][0] = packh2(sacc[2 * kk][0],     sacc[2 * kk][1]);
            ph[kk][1] = packh2(sacc[2 * kk][2],     sacc[2 * kk][3]);
            ph[kk][2] = packh2(sacc[2 * kk + 1][0], sacc[2 * kk + 1][1]);
            ph[kk][3] = packh2(sacc[2 * kk + 1][2], sacc[2 * kk + 1][3]);
        }

        CPA_WAIT(0);
        __syncthreads();

        if (kt < qt) load_k(kt + 1);

#pragma unroll
        for (int ng = 0; ng < 8; ng++) {
#pragma unroll
            for (int kk = 0; kk < 4; kk++) {
                uint32_t vf[4];
                int rr = kk * 16 + (lane & 15);
                uint32_t ad = swz256(rr, ng * 2 + (lane >> 4));
                ldm4t(vf, sBv + ad);
#pragma unroll
                for (int hf = 0; hf < 2; hf++) {
                    int nt = ng * 2 + hf;
                    mma16816f(o[nt], ph[kk], vf[hf * 2], vf[hf * 2 + 1]);
                }
            }
        }

        CPA_WAIT(0);
        __syncthreads();
    }

    float inv0 = 1.f / l0, inv1 = 1.f / l1;
    __half* Obf = OAf + (size_t)(b * SEQ + q0) * QW + h * HD;
#pragma unroll
    for (int nt = 0; nt < 16; nt++) {
        int col = nt * 8 + tig * 2;
        *(uint32_t*)(Obf + (size_t)rl * QW + col) = packh2(o[nt][0] * inv0, o[nt][1] * inv0);
        *(uint32_t*)(Obf + (size_t)rh * QW + col) = packh2(o[nt][2] * inv1, o[nt][3] * inv1);
    }
}

// ---------------------------------------------------------------------------
// Launcher — forked-capture streams: V-proj overlaps QK-proj.
// ---------------------------------------------------------------------------
extern "C" void kernel_launch(void* const* d_in, const int* in_sizes, int n_in,
                              void* d_out, int out_size)
{
    const float* x    = (const float*)d_in[0];
    const float* q_w  = (const float*)d_in[2];
    const float* k_w  = (const float*)d_in[3];
    const float* v_w  = (const float*)d_in[4];
    const float* o_w  = (const float*)d_in[5];
    const float* sinp = (const float*)d_in[6];
    const float* cosp = (const float*)d_in[7];
    float* out = (float*)d_out;

    __nv_bfloat16 *xh, *xl, *wh, *wl, *Qh, *Ql, *Kh, *Kl;
    __half *xf, *vwf, *owf, *Vfp, *Afp;
    cudaGetSymbolAddress((void**)&xh, g_xh);
    cudaGetSymbolAddress((void**)&xl, g_xl);
    cudaGetSymbolAddress((void**)&xf, g_xf);
    cudaGetSymbolAddress((void**)&wh, g_wh);
    cudaGetSymbolAddress((void**)&wl, g_wl);
    cudaGetSymbolAddress((void**)&vwf, g_vwf);
    cudaGetSymbolAddress((void**)&owf, g_owf);
    cudaGetSymbolAddress((void**)&Qh, g_Qh);
    cudaGetSymbolAddress((void**)&Ql, g_Ql);
    cudaGetSymbolAddress((void**)&Kh, g_Kh);
    cudaGetSymbolAddress((void**)&Kl, g_Kl);
    cudaGetSymbolAddress((void**)&Vfp, g_Vf);
    cudaGetSymbolAddress((void**)&Afp, g_Af);

    cudaFuncSetAttribute(hmma_gemm_qk, cudaFuncAttributeMaxDynamicSharedMemorySize, QK_SMEM);
    cudaFuncSetAttribute(hmma_gemm_1t<0>, cudaFuncAttributeMaxDynamicSharedMemorySize, OSMEM);
    cudaFuncSetAttribute(hmma_gemm_1t<1>, cudaFuncAttributeMaxDynamicSharedMemorySize, OSMEM);
    cudaFuncSetAttribute(flash_attn_mma, cudaFuncAttributeMaxDynamicSharedMemorySize, AT_SMEM);

    cudaStream_t s2;
    cudaEvent_t e1, e2;
    cudaStreamCreateWithFlags(&s2, cudaStreamNonBlocking);
    cudaEventCreateWithFlags(&e1, cudaEventDisableTiming);
    cudaEventCreateWithFlags(&e2, cudaEventDisableTiming);

    // 1) fused split of all fp32 operands
    split_all<<<(N4_ALL + 255) / 256, 256>>>(x, q_w, k_w, v_w, o_w,
                                             xh, xl, xf, wh, wl, vwf, owf);
    cudaEventRecord(e1, 0);
    cudaStreamWaitEvent(s2, e1, 0);

    // 2) QK projection (bf16 3-term), BM=64, 2-stage, 3 CTA/SM
    hmma_gemm_qk<<<dim3(W2 / 128, MTOT / 64), 128, QK_SMEM>>>(
        xh, xl, wh, wl, Qh, Ql, Kh, Kl, sinp, cosp, MTOT, W2, HID);

    // 3) V projection (1-term fp16) concurrently on s2
    hmma_gemm_1t<1><<<dim3(KVW / 128, MTOT / 64), 128, OSMEM, s2>>>(
        xf, vwf, Vfp, MTOT, KVW, HID);
    cudaEventRecord(e2, s2);
    cudaStreamWaitEvent(0, e2, 0);

    // 4) flash attention — 1024 CTAs, LPT descending-work order
    flash_attn_mma<<<dim3(NQT * 32), 128, AT_SMEM>>>(Qh, Ql, Kh, Kl, Vfp, Afp);

    // 5) output projection (1-term fp16, fp32 out)
    hmma_gemm_1t<0><<<dim3(HID / 128, MTOT / 64), 128, OSMEM>>>(
        Afp, owf, out, MTOT, HID, HID);
}